// round 13
// baseline (speedup 1.0000x reference)
#include <cuda_runtime.h>
#include <cuda_bf16.h>
#include <cstdint>

#define D        256
#define N2MAX    8192
#define TILE     128
#define NB       64
#define NTILES   2080                 // NB*(NB+1)/2
#define NCTA     148
#define NTHR     256
#define PAD      8
#define SSTRIDE  (D + PAD)            // 264 bf16 (odd # of 16B units)
#define SROWB    (SSTRIDE * 2)        // 528 B per row
#define SBYTES   (TILE * SROWB)       // 67584 B per tile

__device__ __align__(16) __nv_bfloat16 g_zn[N2MAX * D];
__device__ float g_S[N2MAX];
__device__ float g_pos[N2MAX / 2];
__device__ int   g_c1 = 0, g_c2 = 0, g_c3 = 0;

__device__ __forceinline__ uint32_t smem_u32(const void* p) {
    uint32_t a;
    asm("{ .reg .u64 t; cvta.to.shared.u64 t, %1; cvt.u32.u64 %0, t; }" : "=r"(a) : "l"(p));
    return a;
}
#define CP_ASYNC16(d, s) \
    asm volatile("cp.async.cg.shared.global [%0], [%1], 16;" :: "r"(d), "l"(s) : "memory")
#define CP_COMMIT()  asm volatile("cp.async.commit_group;" ::: "memory")
#define CP_WAIT0()   asm volatile("cp.async.wait_group 0;" ::: "memory")
#define LDSM4(r0, r1, r2, r3, a) \
    asm volatile("ldmatrix.sync.aligned.m8n8.x4.shared.b16 {%0,%1,%2,%3}, [%4];" \
                 : "=r"(r0), "=r"(r1), "=r"(r2), "=r"(r3) : "r"(a))
#define MMA(d, a, b) \
    asm volatile("mma.sync.aligned.m16n8k16.row.col.f32.bf16.bf16.f32 " \
                 "{%0,%1,%2,%3},{%4,%5,%6,%7},{%8,%9},{%0,%1,%2,%3};" \
                 : "+f"((d)[0]), "+f"((d)[1]), "+f"((d)[2]), "+f"((d)[3]) \
                 : "r"((a)[0]), "r"((a)[1]), "r"((a)[2]), "r"((a)[3]), \
                   "r"((b)[0]), "r"((b)[1]))

#define EC1 0.69314718f
#define EC2 0.24022651f
#define EC3 0.05550411f
#define EC4 0.00961813f
#define EXPSTEP(x, e) { \
    float y = fmaf((x), 2.8853901f, -2.8853901f); \
    float z = __fadd_rn(y, 12582912.0f); \
    float f = y - __fadd_rn(z, -12582912.0f); \
    float p = fmaf(f, EC4, EC3); \
    p = fmaf(f, p, EC2); \
    p = fmaf(f, p, EC1); \
    p = fmaf(f, p, 1.0f); \
    (e) = __int_as_float(__float_as_int(p) + (__float_as_int(z) << 23)); }

__device__ __forceinline__ void load_tile_async(uint32_t sbase, int row0, int tid) {
    #pragma unroll
    for (int i = 0; i < 16; i++) {
        int chunk = i * NTHR + tid;          // 4096 x 16B
        int r   = chunk >> 5;
        int c16 = chunk & 31;
        const char* src = (const char*)(g_zn + (size_t)(row0 + r) * D) + c16 * 16;
        CP_ASYNC16(sbase + (uint32_t)(r * SROWB + c16 * 16), src);
    }
}

__device__ __forceinline__ void map_tile(int T, int& i, int& j) {
    int pair = T / 65;
    int s    = T - pair * 65;
    int n1   = NB - pair;
    if (s < n1) { i = pair;          j = pair + s; }
    else        { i = NB - 1 - pair; j = i + (s - n1); }
}

// normalize one (zi_r, zj_r) pair held in registers; write bf16 rows + pos.
__device__ __forceinline__ void norm_pair(
    int r, int N, int lane,
    float4 a0, float4 a1, float4 b0, float4 b1)
{
    float sa = a0.x*a0.x+a0.y*a0.y+a0.z*a0.z+a0.w*a0.w + a1.x*a1.x+a1.y*a1.y+a1.z*a1.z+a1.w*a1.w;
    float sb = b0.x*b0.x+b0.y*b0.y+b0.z*b0.z+b0.w*b0.w + b1.x*b1.x+b1.y*b1.y+b1.z*b1.z+b1.w*b1.w;
    float dt = a0.x*b0.x+a0.y*b0.y+a0.z*b0.z+a0.w*b0.w + a1.x*b1.x+a1.y*b1.y+a1.z*b1.z+a1.w*b1.w;
    #pragma unroll
    for (int m = 16; m; m >>= 1) {
        sa += __shfl_xor_sync(0xffffffffu, sa, m);
        sb += __shfl_xor_sync(0xffffffffu, sb, m);
        dt += __shfl_xor_sync(0xffffffffu, dt, m);
    }
    float na = fmaxf(sqrtf(sa), 1e-8f);
    float nb = fmaxf(sqrtf(sb), 1e-8f);
    if (lane == 0) g_pos[r] = 2.0f * dt / (na * nb);
    float ia = 1.0f / na, ib = 1.0f / nb;
    __nv_bfloat162* oa = (__nv_bfloat162*)(g_zn + (size_t)r * D);
    oa[2*lane]      = __nv_bfloat162(__float2bfloat16_rn(a0.x*ia), __float2bfloat16_rn(a0.y*ia));
    oa[2*lane + 1]  = __nv_bfloat162(__float2bfloat16_rn(a0.z*ia), __float2bfloat16_rn(a0.w*ia));
    oa[2*lane + 64] = __nv_bfloat162(__float2bfloat16_rn(a1.x*ia), __float2bfloat16_rn(a1.y*ia));
    oa[2*lane + 65] = __nv_bfloat162(__float2bfloat16_rn(a1.z*ia), __float2bfloat16_rn(a1.w*ia));
    __nv_bfloat162* ob = (__nv_bfloat162*)(g_zn + (size_t)(r + N) * D);
    ob[2*lane]      = __nv_bfloat162(__float2bfloat16_rn(b0.x*ib), __float2bfloat16_rn(b0.y*ib));
    ob[2*lane + 1]  = __nv_bfloat162(__float2bfloat16_rn(b0.z*ib), __float2bfloat16_rn(b0.w*ib));
    ob[2*lane + 64] = __nv_bfloat162(__float2bfloat16_rn(b1.x*ib), __float2bfloat16_rn(b1.y*ib));
    ob[2*lane + 65] = __nv_bfloat162(__float2bfloat16_rn(b1.z*ib), __float2bfloat16_rn(b1.w*ib));
}

// ---------------------------------------------------------------------------
// Fused: normalize (2-row ILP) -> grid barrier -> triangular GEMM -> grid
// barrier -> parallel reduce.
// ---------------------------------------------------------------------------
__global__ void __launch_bounds__(NTHR, 1) fused_kernel(
    const float* __restrict__ zi, const float* __restrict__ zj,
    float* __restrict__ out, int N)
{
    extern __shared__ char sm[];
    const int tid  = threadIdx.x;
    const int wid  = tid >> 5;
    const int lane = tid & 31;
    const int N2   = 2 * N;

    // ---- Phase A: zero g_S + normalize (two independent row-pairs in flight) ----
    for (int idx = blockIdx.x * NTHR + tid; idx < N2; idx += NCTA * NTHR)
        g_S[idx] = 0.0f;

    const int wstep = NCTA * 8;
    for (int r = blockIdx.x * 8 + wid; r < N; r += 2 * wstep) {
        const int r2 = r + wstep;
        const float4* a = (const float4*)(zi + (size_t)r * D);
        const float4* b = (const float4*)(zj + (size_t)r * D);
        float4 a0 = a[lane], a1 = a[lane + 32];
        float4 b0 = b[lane], b1 = b[lane + 32];
        float4 c0, c1, d0, d1;
        if (r2 < N) {
            const float4* c = (const float4*)(zi + (size_t)r2 * D);
            const float4* d = (const float4*)(zj + (size_t)r2 * D);
            c0 = c[lane]; c1 = c[lane + 32];
            d0 = d[lane]; d1 = d[lane + 32];
        }
        norm_pair(r, N, lane, a0, a1, b0, b1);
        if (r2 < N) norm_pair(r2, N, lane, c0, c1, d0, d1);
    }

    // ---- grid barrier 1 (volatile-poll; atomic only for the increment) ----
    __syncthreads();
    if (tid == 0) {
        __threadfence();
        atomicAdd(&g_c1, 1);
        while (*(volatile int*)&g_c1 < NCTA) { }
        __threadfence();
    }
    __syncthreads();

    // ---- Phase B: triangular GEMM, warp grid 2 (m) x 4 (n), tile 64x32 ----
    {
        const int wm = wid & 1;
        const int wn = wid >> 1;
        const int lo = (NTILES * blockIdx.x) / NCTA;
        const int hi = (NTILES * (blockIdx.x + 1)) / NCTA;

        const uint32_t aB  = smem_u32(sm);
        const uint32_t bB0 = aB + SBYTES;
        const uint32_t bB1 = aB + 2 * SBYTES;
        const uint32_t aAddr = aB +
            (uint32_t)((wm * 64 + (lane & 15)) * SROWB + (lane >> 4) * 16);
        const uint32_t bOff =
            (uint32_t)((wn * 32 + (lane & 7) + ((lane >> 4) << 3)) * SROWB +
                       ((lane >> 3) & 1) * 16);

        float rs[8] = {0,0,0,0,0,0,0,0};

        int i, j;
        map_tile(lo, i, j);
        load_tile_async(aB, i * TILE, tid);
        load_tile_async(bB0, j * TILE, tid);
        CP_COMMIT(); CP_WAIT0();
        __syncthreads();

        for (int t = lo; t < hi; t++) {
            int ni = -1, nj = -1;
            if (t + 1 < hi) map_tile(t + 1, ni, nj);
            const uint32_t bCur  = ((t - lo) & 1) ? bB1 : bB0;
            const uint32_t bNext = ((t - lo) & 1) ? bB0 : bB1;
            if (t + 1 < hi) { load_tile_async(bNext, nj * TILE, tid); CP_COMMIT(); }

            const uint32_t bAddr = bCur + bOff;
            float acc[16][4];
            #pragma unroll
            for (int q = 0; q < 16; q++)
                #pragma unroll
                for (int v = 0; v < 4; v++) acc[q][v] = 0.0f;

            // explicit double-buffered fragment pipeline over 16 k-steps
            uint32_t af[2][4][4], bfn[2][4][2];
            #pragma unroll
            for (int mt = 0; mt < 4; mt++)
                LDSM4(af[0][mt][0], af[0][mt][1], af[0][mt][2], af[0][mt][3],
                      aAddr + (uint32_t)(mt * 16 * SROWB));
            LDSM4(bfn[0][0][0], bfn[0][0][1], bfn[0][1][0], bfn[0][1][1], bAddr);
            LDSM4(bfn[0][2][0], bfn[0][2][1], bfn[0][3][0], bfn[0][3][1],
                  bAddr + (uint32_t)(16 * SROWB));

            #pragma unroll
            for (int ks = 0; ks < 16; ks++) {
                const int cur = ks & 1, nxt = cur ^ 1;
                if (ks < 15) {
                    #pragma unroll
                    for (int mt = 0; mt < 4; mt++)
                        LDSM4(af[nxt][mt][0], af[nxt][mt][1], af[nxt][mt][2], af[nxt][mt][3],
                              aAddr + (uint32_t)(mt * 16 * SROWB + (ks + 1) * 32));
                    LDSM4(bfn[nxt][0][0], bfn[nxt][0][1], bfn[nxt][1][0], bfn[nxt][1][1],
                          bAddr + (uint32_t)((ks + 1) * 32));
                    LDSM4(bfn[nxt][2][0], bfn[nxt][2][1], bfn[nxt][3][0], bfn[nxt][3][1],
                          bAddr + (uint32_t)(16 * SROWB + (ks + 1) * 32));
                }
                #pragma unroll
                for (int mt = 0; mt < 4; mt++)
                    #pragma unroll
                    for (int nt = 0; nt < 4; nt++)
                        MMA(acc[mt * 4 + nt], af[cur][mt], bfn[cur][nt]);
            }

            // inline epilogue
            float cs[8] = {0,0,0,0,0,0,0,0};
            #pragma unroll
            for (int q = 0; q < 16; q++) {
                const int mt = q >> 2, nt = q & 3;
                #pragma unroll
                for (int v = 0; v < 4; v++) {
                    float e;
                    EXPSTEP(acc[q][v], e);
                    rs[mt * 2 + (v >> 1)] += e;
                    cs[nt * 2 + (v & 1)]  += e;
                }
            }
            if (j != i) {
                #pragma unroll
                for (int q = 0; q < 8; q++) {
                    cs[q] += __shfl_xor_sync(0xffffffffu, cs[q], 4);
                    cs[q] += __shfl_xor_sync(0xffffffffu, cs[q], 8);
                    cs[q] += __shfl_xor_sync(0xffffffffu, cs[q], 16);
                }
                if (lane < 4) {
                    const int C0 = j * TILE + wn * 32 + lane * 2;
                    #pragma unroll
                    for (int nt = 0; nt < 4; nt++) {
                        atomicAdd(&g_S[C0 + nt * 8],     cs[nt * 2]);
                        atomicAdd(&g_S[C0 + nt * 8 + 1], cs[nt * 2 + 1]);
                    }
                }
            }
            if (t + 1 >= hi || ni != i) {
                #pragma unroll
                for (int q = 0; q < 8; q++) {
                    rs[q] += __shfl_xor_sync(0xffffffffu, rs[q], 1);
                    rs[q] += __shfl_xor_sync(0xffffffffu, rs[q], 2);
                }
                if ((lane & 3) == 0) {
                    const int R0 = i * TILE + wm * 64;
                    #pragma unroll
                    for (int mt = 0; mt < 4; mt++) {
                        atomicAdd(&g_S[R0 + mt * 16 +     (lane >> 2)], rs[mt * 2]);
                        atomicAdd(&g_S[R0 + mt * 16 + 8 + (lane >> 2)], rs[mt * 2 + 1]);
                    }
                }
                #pragma unroll
                for (int q = 0; q < 8; q++) rs[q] = 0.0f;
            }

            if (t + 1 < hi) {
                if (ni != i) {
                    __syncthreads();
                    load_tile_async(aB, ni * TILE, tid);
                    CP_COMMIT();
                }
                CP_WAIT0();
                __syncthreads();
            }
            i = ni; j = nj;
            if (ni < 0) break;
        }
    }

    // ---- grid barrier 2, then parallel reduce across all CTAs ----
    __syncthreads();
    if (tid == 0) {
        if (blockIdx.x == 0) out[0] = 0.0f;   // out is poisoned 0xAA
        __threadfence();
        atomicAdd(&g_c2, 1);
        while (*(volatile int*)&g_c2 < NCTA) { }
        __threadfence();
    }
    __syncthreads();

    {
        __shared__ double sh[NTHR];
        const int r0 = (N2 * blockIdx.x) / NCTA;
        const int r1 = (N2 * (blockIdx.x + 1)) / NCTA;
        const int q0 = (N * blockIdx.x) / NCTA;
        const int q1 = (N * (blockIdx.x + 1)) / NCTA;
        double local = 0.0;
        for (int idx = r0 + tid; idx < r1; idx += NTHR)
            local += (double)(2.0f + __logf(g_S[idx] - 1.0f));
        for (int r = q0 + tid; r < q1; r += NTHR)
            local -= 2.0 * (double)g_pos[r];
        sh[tid] = local;
        __syncthreads();
        #pragma unroll
        for (int s2 = NTHR / 2; s2; s2 >>= 1) {
            if (tid < s2) sh[tid] += sh[tid + s2];
            __syncthreads();
        }
        if (tid == 0)
            atomicAdd(out, (float)(sh[0] / (double)N2));
    }

    // ---- completion + barrier reset for graph replay ----
    if (tid == 0) {
        __threadfence();
        atomicAdd(&g_c3, 1);
        if (blockIdx.x == 0) {
            while (*(volatile int*)&g_c3 < NCTA) { }
            g_c1 = 0; g_c2 = 0; g_c3 = 0;
            __threadfence();
        }
    }
}

// ---------------------------------------------------------------------------
extern "C" void kernel_launch(void* const* d_in, const int* in_sizes, int n_in,
                              void* d_out, int out_size)
{
    const float* zi = (const float*)d_in[0];
    const float* zj = (const float*)d_in[1];
    int N = in_sizes[0] / D;      // 4096

    size_t smem = 3 * (size_t)SBYTES;   // 202752 B
    cudaFuncSetAttribute(fused_kernel,
                         cudaFuncAttributeMaxDynamicSharedMemorySize, (int)smem);
    fused_kernel<<<NCTA, NTHR, smem>>>(zi, zj, (float*)d_out, N);
}

// round 14
// speedup vs baseline: 1.0517x; 1.0517x over previous
#include <cuda_runtime.h>
#include <cuda_bf16.h>
#include <cstdint>

#define D        256
#define N2MAX    8192
#define TILE     128
#define NB       64
#define NTILES   2080                 // NB*(NB+1)/2
#define NCTA     148
#define NTHR     256
#define PAD      8
#define SSTRIDE  (D + PAD)            // 264 bf16 (odd # of 16B units)
#define SROWB    (SSTRIDE * 2)        // 528 B per row
#define SBYTES   (TILE * SROWB)       // 67584 B per tile

__device__ __align__(16) __nv_bfloat16 g_zn[N2MAX * D];
__device__ float g_S[N2MAX];
__device__ float g_pos[N2MAX / 2];
__device__ int   g_c1 = 0, g_c2 = 0, g_c3 = 0;

__device__ __forceinline__ uint32_t smem_u32(const void* p) {
    uint32_t a;
    asm("{ .reg .u64 t; cvta.to.shared.u64 t, %1; cvt.u32.u64 %0, t; }" : "=r"(a) : "l"(p));
    return a;
}
#define CP_ASYNC16(d, s) \
    asm volatile("cp.async.cg.shared.global [%0], [%1], 16;" :: "r"(d), "l"(s) : "memory")
#define CP_COMMIT()  asm volatile("cp.async.commit_group;" ::: "memory")
#define CP_WAIT0()   asm volatile("cp.async.wait_group 0;" ::: "memory")
#define LDSM4(r0, r1, r2, r3, a) \
    asm volatile("ldmatrix.sync.aligned.m8n8.x4.shared.b16 {%0,%1,%2,%3}, [%4];" \
                 : "=r"(r0), "=r"(r1), "=r"(r2), "=r"(r3) : "r"(a))
#define MMA(d, a, b) \
    asm volatile("mma.sync.aligned.m16n8k16.row.col.f32.bf16.bf16.f32 " \
                 "{%0,%1,%2,%3},{%4,%5,%6,%7},{%8,%9},{%0,%1,%2,%3};" \
                 : "+f"((d)[0]), "+f"((d)[1]), "+f"((d)[2]), "+f"((d)[3]) \
                 : "r"((a)[0]), "r"((a)[1]), "r"((a)[2]), "r"((a)[3]), \
                   "r"((b)[0]), "r"((b)[1]))

#define EC1 0.69314718f
#define EC2 0.24022651f
#define EC3 0.05550411f
#define EC4 0.00961813f
#define EXPSTEP(x, e) { \
    float y = fmaf((x), 2.8853901f, -2.8853901f); \
    float z = __fadd_rn(y, 12582912.0f); \
    float f = y - __fadd_rn(z, -12582912.0f); \
    float p = fmaf(f, EC4, EC3); \
    p = fmaf(f, p, EC2); \
    p = fmaf(f, p, EC1); \
    p = fmaf(f, p, 1.0f); \
    (e) = __int_as_float(__float_as_int(p) + (__float_as_int(z) << 23)); }

__device__ __forceinline__ void load_tile_async(uint32_t sbase, int row0, int tid) {
    #pragma unroll
    for (int i = 0; i < 16; i++) {
        int chunk = i * NTHR + tid;          // 4096 x 16B
        int r   = chunk >> 5;
        int c16 = chunk & 31;
        const char* src = (const char*)(g_zn + (size_t)(row0 + r) * D) + c16 * 16;
        CP_ASYNC16(sbase + (uint32_t)(r * SROWB + c16 * 16), src);
    }
}

__device__ __forceinline__ void map_tile(int T, int& i, int& j) {
    int pair = T / 65;
    int s    = T - pair * 65;
    int n1   = NB - pair;
    if (s < n1) { i = pair;          j = pair + s; }
    else        { i = NB - 1 - pair; j = i + (s - n1); }
}

// ---------------------------------------------------------------------------
// Fused: normalize -> grid barrier -> triangular GEMM (8 warps, 64x32 tiles,
// explicit fragment double-buffer pipeline) -> grid barrier -> PARALLEL reduce.
// ---------------------------------------------------------------------------
__global__ void __launch_bounds__(NTHR, 1) fused_kernel(
    const float* __restrict__ zi, const float* __restrict__ zj,
    float* __restrict__ out, int N)
{
    extern __shared__ char sm[];
    const int tid  = threadIdx.x;
    const int wid  = tid >> 5;
    const int lane = tid & 31;
    const int N2   = 2 * N;

    // ---- Phase A: zero g_S + normalize ----
    for (int idx = blockIdx.x * NTHR + tid; idx < N2; idx += NCTA * NTHR)
        g_S[idx] = 0.0f;

    #pragma unroll 2
    for (int r = blockIdx.x * 8 + wid; r < N; r += NCTA * 8) {
        const float4* a = (const float4*)(zi + (size_t)r * D);
        const float4* b = (const float4*)(zj + (size_t)r * D);
        float4 a0 = a[lane], a1 = a[lane + 32];
        float4 b0 = b[lane], b1 = b[lane + 32];
        float sa = a0.x*a0.x+a0.y*a0.y+a0.z*a0.z+a0.w*a0.w + a1.x*a1.x+a1.y*a1.y+a1.z*a1.z+a1.w*a1.w;
        float sb = b0.x*b0.x+b0.y*b0.y+b0.z*b0.z+b0.w*b0.w + b1.x*b1.x+b1.y*b1.y+b1.z*b1.z+b1.w*b1.w;
        float dt = a0.x*b0.x+a0.y*b0.y+a0.z*b0.z+a0.w*b0.w + a1.x*b1.x+a1.y*b1.y+a1.z*b1.z+a1.w*b1.w;
        #pragma unroll
        for (int m = 16; m; m >>= 1) {
            sa += __shfl_xor_sync(0xffffffffu, sa, m);
            sb += __shfl_xor_sync(0xffffffffu, sb, m);
            dt += __shfl_xor_sync(0xffffffffu, dt, m);
        }
        float na = fmaxf(sqrtf(sa), 1e-8f);
        float nb = fmaxf(sqrtf(sb), 1e-8f);
        if (lane == 0) g_pos[r] = 2.0f * dt / (na * nb);
        float ia = 1.0f / na, ib = 1.0f / nb;
        __nv_bfloat162* oa = (__nv_bfloat162*)(g_zn + (size_t)r * D);
        oa[2*lane]      = __nv_bfloat162(__float2bfloat16_rn(a0.x*ia), __float2bfloat16_rn(a0.y*ia));
        oa[2*lane + 1]  = __nv_bfloat162(__float2bfloat16_rn(a0.z*ia), __float2bfloat16_rn(a0.w*ia));
        oa[2*lane + 64] = __nv_bfloat162(__float2bfloat16_rn(a1.x*ia), __float2bfloat16_rn(a1.y*ia));
        oa[2*lane + 65] = __nv_bfloat162(__float2bfloat16_rn(a1.z*ia), __float2bfloat16_rn(a1.w*ia));
        __nv_bfloat162* ob = (__nv_bfloat162*)(g_zn + (size_t)(r + N) * D);
        ob[2*lane]      = __nv_bfloat162(__float2bfloat16_rn(b0.x*ib), __float2bfloat16_rn(b0.y*ib));
        ob[2*lane + 1]  = __nv_bfloat162(__float2bfloat16_rn(b0.z*ib), __float2bfloat16_rn(b0.w*ib));
        ob[2*lane + 64] = __nv_bfloat162(__float2bfloat16_rn(b1.x*ib), __float2bfloat16_rn(b1.y*ib));
        ob[2*lane + 65] = __nv_bfloat162(__float2bfloat16_rn(b1.z*ib), __float2bfloat16_rn(b1.w*ib));
    }

    // ---- grid barrier 1 ----
    __syncthreads();
    if (tid == 0) {
        __threadfence();
        atomicAdd(&g_c1, 1);
        while (atomicAdd(&g_c1, 0) < NCTA) { }
        __threadfence();
    }
    __syncthreads();

    // ---- Phase B: triangular GEMM, warp grid 2 (m) x 4 (n), tile 64x32 ----
    {
        const int wm = wid & 1;
        const int wn = wid >> 1;
        const int lo = (NTILES * blockIdx.x) / NCTA;
        const int hi = (NTILES * (blockIdx.x + 1)) / NCTA;

        const uint32_t aB  = smem_u32(sm);
        const uint32_t bB0 = aB + SBYTES;
        const uint32_t bB1 = aB + 2 * SBYTES;
        const uint32_t aAddr = aB +
            (uint32_t)((wm * 64 + (lane & 15)) * SROWB + (lane >> 4) * 16);
        const uint32_t bOff =
            (uint32_t)((wn * 32 + (lane & 7) + ((lane >> 4) << 3)) * SROWB +
                       ((lane >> 3) & 1) * 16);

        float rs[8] = {0,0,0,0,0,0,0,0};

        int i, j;
        map_tile(lo, i, j);
        load_tile_async(aB, i * TILE, tid);
        load_tile_async(bB0, j * TILE, tid);
        CP_COMMIT(); CP_WAIT0();
        __syncthreads();

        for (int t = lo; t < hi; t++) {
            int ni = -1, nj = -1;
            if (t + 1 < hi) map_tile(t + 1, ni, nj);
            const uint32_t bCur  = ((t - lo) & 1) ? bB1 : bB0;
            const uint32_t bNext = ((t - lo) & 1) ? bB0 : bB1;
            if (t + 1 < hi) { load_tile_async(bNext, nj * TILE, tid); CP_COMMIT(); }

            const uint32_t bAddr = bCur + bOff;
            float acc[16][4];
            #pragma unroll
            for (int q = 0; q < 16; q++)
                #pragma unroll
                for (int v = 0; v < 4; v++) acc[q][v] = 0.0f;

            // explicit double-buffered fragment pipeline over 16 k-steps
            uint32_t af[2][4][4], bfn[2][4][2];
            #pragma unroll
            for (int mt = 0; mt < 4; mt++)
                LDSM4(af[0][mt][0], af[0][mt][1], af[0][mt][2], af[0][mt][3],
                      aAddr + (uint32_t)(mt * 16 * SROWB));
            LDSM4(bfn[0][0][0], bfn[0][0][1], bfn[0][1][0], bfn[0][1][1], bAddr);
            LDSM4(bfn[0][2][0], bfn[0][2][1], bfn[0][3][0], bfn[0][3][1],
                  bAddr + (uint32_t)(16 * SROWB));

            #pragma unroll
            for (int ks = 0; ks < 16; ks++) {
                const int cur = ks & 1, nxt = cur ^ 1;
                if (ks < 15) {
                    #pragma unroll
                    for (int mt = 0; mt < 4; mt++)
                        LDSM4(af[nxt][mt][0], af[nxt][mt][1], af[nxt][mt][2], af[nxt][mt][3],
                              aAddr + (uint32_t)(mt * 16 * SROWB + (ks + 1) * 32));
                    LDSM4(bfn[nxt][0][0], bfn[nxt][0][1], bfn[nxt][1][0], bfn[nxt][1][1],
                          bAddr + (uint32_t)((ks + 1) * 32));
                    LDSM4(bfn[nxt][2][0], bfn[nxt][2][1], bfn[nxt][3][0], bfn[nxt][3][1],
                          bAddr + (uint32_t)(16 * SROWB + (ks + 1) * 32));
                }
                #pragma unroll
                for (int mt = 0; mt < 4; mt++)
                    #pragma unroll
                    for (int nt = 0; nt < 4; nt++)
                        MMA(acc[mt * 4 + nt], af[cur][mt], bfn[cur][nt]);
            }

            // inline epilogue
            float cs[8] = {0,0,0,0,0,0,0,0};
            #pragma unroll
            for (int q = 0; q < 16; q++) {
                const int mt = q >> 2, nt = q & 3;
                #pragma unroll
                for (int v = 0; v < 4; v++) {
                    float e;
                    EXPSTEP(acc[q][v], e);
                    rs[mt * 2 + (v >> 1)] += e;
                    cs[nt * 2 + (v & 1)]  += e;
                }
            }
            if (j != i) {
                #pragma unroll
                for (int q = 0; q < 8; q++) {
                    cs[q] += __shfl_xor_sync(0xffffffffu, cs[q], 4);
                    cs[q] += __shfl_xor_sync(0xffffffffu, cs[q], 8);
                    cs[q] += __shfl_xor_sync(0xffffffffu, cs[q], 16);
                }
                if (lane < 4) {
                    const int C0 = j * TILE + wn * 32 + lane * 2;
                    #pragma unroll
                    for (int nt = 0; nt < 4; nt++) {
                        atomicAdd(&g_S[C0 + nt * 8],     cs[nt * 2]);
                        atomicAdd(&g_S[C0 + nt * 8 + 1], cs[nt * 2 + 1]);
                    }
                }
            }
            if (t + 1 >= hi || ni != i) {
                #pragma unroll
                for (int q = 0; q < 8; q++) {
                    rs[q] += __shfl_xor_sync(0xffffffffu, rs[q], 1);
                    rs[q] += __shfl_xor_sync(0xffffffffu, rs[q], 2);
                }
                if ((lane & 3) == 0) {
                    const int R0 = i * TILE + wm * 64;
                    #pragma unroll
                    for (int mt = 0; mt < 4; mt++) {
                        atomicAdd(&g_S[R0 + mt * 16 +     (lane >> 2)], rs[mt * 2]);
                        atomicAdd(&g_S[R0 + mt * 16 + 8 + (lane >> 2)], rs[mt * 2 + 1]);
                    }
                }
                #pragma unroll
                for (int q = 0; q < 8; q++) rs[q] = 0.0f;
            }

            if (t + 1 < hi) {
                if (ni != i) {
                    __syncthreads();
                    load_tile_async(aB, ni * TILE, tid);
                    CP_COMMIT();
                }
                CP_WAIT0();
                __syncthreads();
            }
            i = ni; j = nj;
            if (ni < 0) break;
        }
    }

    // ---- grid barrier 2, then PARALLEL reduce across all CTAs ----
    __syncthreads();
    if (tid == 0) {
        if (blockIdx.x == 0) out[0] = 0.0f;   // out is poisoned 0xAA
        __threadfence();
        atomicAdd(&g_c2, 1);
        while (atomicAdd(&g_c2, 0) < NCTA) { }
        __threadfence();
    }
    __syncthreads();

    {
        __shared__ double sh[NTHR];
        const int r0 = (N2 * blockIdx.x) / NCTA;
        const int r1 = (N2 * (blockIdx.x + 1)) / NCTA;
        const int q0 = (N * blockIdx.x) / NCTA;
        const int q1 = (N * (blockIdx.x + 1)) / NCTA;
        double local = 0.0;
        for (int idx = r0 + tid; idx < r1; idx += NTHR)
            local += (double)(2.0f + __logf(g_S[idx] - 1.0f));
        for (int r = q0 + tid; r < q1; r += NTHR)
            local -= 2.0 * (double)g_pos[r];
        sh[tid] = local;
        __syncthreads();
        #pragma unroll
        for (int s2 = NTHR / 2; s2; s2 >>= 1) {
            if (tid < s2) sh[tid] += sh[tid + s2];
            __syncthreads();
        }
        if (tid == 0)
            atomicAdd(out, (float)(sh[0] / (double)N2));
    }

    // ---- completion + barrier reset for graph replay ----
    if (tid == 0) {
        __threadfence();
        atomicAdd(&g_c3, 1);
        if (blockIdx.x == 0) {
            while (atomicAdd(&g_c3, 0) < NCTA) { }
            g_c1 = 0; g_c2 = 0; g_c3 = 0;
            __threadfence();
        }
    }
}

// ---------------------------------------------------------------------------
extern "C" void kernel_launch(void* const* d_in, const int* in_sizes, int n_in,
                              void* d_out, int out_size)
{
    const float* zi = (const float*)d_in[0];
    const float* zj = (const float*)d_in[1];
    int N = in_sizes[0] / D;      // 4096

    size_t smem = 3 * (size_t)SBYTES;   // 202752 B
    cudaFuncSetAttribute(fused_kernel,
                         cudaFuncAttributeMaxDynamicSharedMemorySize, (int)smem);
    fused_kernel<<<NCTA, NTHR, smem>>>(zi, zj, (float*)d_out, N);
}